// round 13
// baseline (speedup 1.0000x reference)
#include <cuda_runtime.h>
#include <cuda_fp16.h>
#include <math.h>
#include <stdint.h>

// ---------------- problem constants ----------------
#define T_TOK 4096
#define S_LEN 2048
#define DIMM 1024
#define QC 128
#define KVC 128
#define KROPE 64
#define HD 128

// log2(10000) = 13.287712379549449
#define QR_EXP 0.8304820237218406f   // /16  (q rope, head_dim 32)
#define KR_EXP 0.4152410118609203f   // /32  (k rope, head_dim 64)

// ---------------- scratch ----------------
__device__ float  g_dqkv[(size_t)T_TOK * 320];
__device__ float  g_krope[T_TOK * KROPE];
__device__ __half g_qrawh[(size_t)T_TOK * 1024];
__device__ __half g_knh[(size_t)T_TOK * 512];        // k_nope up-proj out
__device__ __half g_xh[(size_t)T_TOK * DIMM];
__device__ __half g_wqkv[DIMM * 320];
__device__ float  g_bqkv[320];
__device__ __half g_wuq[QC * 1024];
__device__ __half g_wukn[KVC * 512];                 // W_uk (k_nope cols)
__device__ __half g_wukv[KVC * 2048];                // W_uv (v cols)
__device__ __half g_woh[(size_t)2048 * DIMM];        // W_o fp16 [k][n]
__device__ __half g_wpack[(size_t)1024 * 1024];      // packed W_uv@W_o
__device__ float  g_beff[1024];                      // b_o + b_v @ W_o
__device__ __half g_cqh[T_TOK * QC];
__device__ __half g_ckvh[T_TOK * KVC];
__device__ __half g_ckvT[(size_t)2 * KVC * S_LEN];   // [b][128][2048] (ckvn^T)
__device__ __half g_qh[(size_t)16 * S_LEN * HD];
__device__ __half g_kh[(size_t)16 * S_LEN * HD];
__device__ __half g_lath[(size_t)T_TOK * 1024];      // latent attn out [t][h*128+d]

// ---------------- helpers ----------------
__device__ __forceinline__ void mma_f16(float c[4], const uint32_t a[4], const uint32_t b[2]) {
    asm volatile(
        "mma.sync.aligned.m16n8k16.row.col.f32.f16.f16.f32 "
        "{%0,%1,%2,%3},{%4,%5,%6,%7},{%8,%9},{%0,%1,%2,%3};"
        : "+f"(c[0]), "+f"(c[1]), "+f"(c[2]), "+f"(c[3])
        : "r"(a[0]), "r"(a[1]), "r"(a[2]), "r"(a[3]), "r"(b[0]), "r"(b[1]));
}

__device__ __forceinline__ void ldsm4(uint32_t r[4], uint32_t saddr) {
    asm volatile("ldmatrix.sync.aligned.m8n8.x4.shared.b16 {%0,%1,%2,%3}, [%4];"
        : "=r"(r[0]), "=r"(r[1]), "=r"(r[2]), "=r"(r[3]) : "r"(saddr));
}
__device__ __forceinline__ void ldsm4t(uint32_t r[4], uint32_t saddr) {
    asm volatile("ldmatrix.sync.aligned.m8n8.x4.trans.shared.b16 {%0,%1,%2,%3}, [%4];"
        : "=r"(r[0]), "=r"(r[1]), "=r"(r[2]), "=r"(r[3]) : "r"(saddr));
}

__device__ __forceinline__ void cp_async16(void* smem_dst, const void* gsrc) {
    uint32_t s = (uint32_t)__cvta_generic_to_shared(smem_dst);
    asm volatile("cp.async.ca.shared.global [%0], [%1], 16;\n" :: "r"(s), "l"(gsrc));
}
#define CP_COMMIT() asm volatile("cp.async.commit_group;\n" ::: "memory")
#define CP_WAIT1()  asm volatile("cp.async.wait_group 1;\n" ::: "memory")

__device__ __forceinline__ uint32_t packh2(float lo, float hi) {
    __half2 h = __floats2half2_rn(lo, hi);
    return *(uint32_t*)&h;
}

// ---------------- fused f32 -> f16 conversion ----------------
#define CV_X   (T_TOK * DIMM)
#define CV_DQ  (DIMM * QC)
#define CV_DKV (DIMM * 192)
#define CV_UQ  (QC * 1024)
#define CV_UK  (KVC * 2560)
#define CV_WO  (2048 * DIMM)
#define CV_TOTAL (CV_X + CV_DQ + CV_DKV + CV_UQ + CV_UK + CV_WO)
#define CV_QUADS (CV_TOTAL / 4)

__global__ __launch_bounds__(256) void convert_all(
    const float* __restrict__ x,   const float* __restrict__ wdq,
    const float* __restrict__ wdkv,const float* __restrict__ wuq,
    const float* __restrict__ wuk, const float* __restrict__ wo,
    const float* __restrict__ bdq, const float* __restrict__ bdkv,
    __half* __restrict__ xh,   __half* __restrict__ wqkvh,
    __half* __restrict__ wuqh, __half* __restrict__ wuknh,
    __half* __restrict__ wukvh,__half* __restrict__ woh,
    float* __restrict__ bqkv)
{
    if (blockIdx.x == 0) {
        int tix = threadIdx.x;
        if (tix < 320) bqkv[tix] = (tix < 128) ? bdq[tix] : bdkv[tix - 128];
        if (tix < 64)  bqkv[256 + tix] = bdkv[128 + tix];
    }
    long long i = ((long long)blockIdx.x * 256 + threadIdx.x) * 4;
    if (i >= CV_TOTAL) return;
    long long off = i;
    const float* src;
    __half* dst;
    long long didx;
    if (off < CV_X) {
        src = x; dst = xh; didx = off;
    } else if ((off -= CV_X) < CV_DQ) {
        src = wdq; dst = wqkvh;
        didx = (off >> 7) * 320 + (off & 127);
    } else if ((off -= CV_DQ) < CV_DKV) {
        src = wdkv; dst = wqkvh;
        didx = (off / 192) * 320 + 128 + (off % 192);
    } else if ((off -= CV_DKV) < CV_UQ) {
        src = wuq; dst = wuqh; didx = off;
    } else if ((off -= CV_UQ) < CV_UK) {
        src = wuk;
        long long row = off / 2560, col = off % 2560;
        if (col < 512) { dst = wuknh; didx = row * 512 + col; }
        else           { dst = wukvh; didx = row * 2048 + (col - 512); }
    } else {
        off -= CV_UK; src = wo; dst = woh; didx = off;
    }
    float4 v = *(const float4*)&src[off];
    *(__half2*)&dst[didx]     = __floats2half2_rn(v.x, v.y);
    *(__half2*)&dst[didx + 2] = __floats2half2_rn(v.z, v.w);
}

// ---------------- b_eff = w_o_b + b_v @ W_o ----------------
__global__ __launch_bounds__(256) void beff_kernel(
    const float* __restrict__ wo, const float* __restrict__ bukuv,
    const float* __restrict__ bo, float* __restrict__ beff)
{
    int n = blockIdx.x * 256 + threadIdx.x;
    float acc = bo[n];
    for (int k = 0; k < 2048; k++)
        acc += bukuv[512 + k] * wo[(size_t)k * 1024 + n];
    beff[n] = acc;
}

// ---------------- fp16 tensor-core GEMM, 3-stage cp.async pipeline ----------------
template<int BN, bool HALF_OUT>
__global__ __launch_bounds__(256, 2) void hgemm(
    const __half* __restrict__ A, const __half* __restrict__ W,
    const float* __restrict__ bias, void* __restrict__ Cv,
    int M, int N, int K)
{
    constexpr int BM = 128, BK = 32, ST = 3;
    constexpr int LDA = BK + 8;
    constexpr int LDB = BN + 8;
    constexpr int WN = BN / 2;
    constexpr int NB = WN / 8;
    constexpr int NB16 = WN / 16;
    __shared__ __half As[ST][BM][LDA];
    __shared__ __half Bs[ST][BK][LDB];

    int tid = threadIdx.x, lane = tid & 31, w = tid >> 5;
    int g = lane >> 2, t = lane & 3;
    int wm = (w >> 1) * 32, wn = (w & 1) * WN;
    int m0 = blockIdx.y * BM, n0 = blockIdx.x * BN;

    int rowX = (lane & 7) + ((lane >> 3) & 1) * 8;
    int colX = (lane >> 4) * 8;

    uint32_t aAddr = (uint32_t)__cvta_generic_to_shared(&As[0][wm + rowX][colX]);
    uint32_t bAddr = (uint32_t)__cvta_generic_to_shared(&Bs[0][rowX][wn + colX]);
    constexpr uint32_t ABUF = BM * LDA * 2;
    constexpr uint32_t BBUF = BK * LDB * 2;

    const __half* Ag = A + (size_t)m0 * K;
    const __half* Wg = W + n0;

    auto load = [&](int k0, int buf) {
        #pragma unroll
        for (int i = tid; i < BM * BK / 8; i += 256) {
            int r = i >> 2, c = (i & 3) * 8;
            cp_async16(&As[buf][r][c], &Ag[(size_t)r * K + k0 + c]);
        }
        #pragma unroll
        for (int i = tid; i < BK * BN / 8; i += 256) {
            int r = i / (BN / 8), c = (i % (BN / 8)) * 8;
            cp_async16(&Bs[buf][r][c], &Wg[(size_t)(k0 + r) * N + c]);
        }
    };

    float c[2][NB][4] = {};

    int nt = K / BK;
    load(0, 0); CP_COMMIT();
    load(BK, 1); CP_COMMIT();

    for (int it = 0; it < nt; it++) {
        int buf = it % 3;
        CP_WAIT1();
        __syncthreads();
        if (it + 2 < nt) load((it + 2) * BK, (it + 2) % 3);
        CP_COMMIT();

        uint32_t af[2][2][4];
        #pragma unroll
        for (int i = 0; i < 2; i++)
            #pragma unroll
            for (int kg = 0; kg < 2; kg++)
                ldsm4(af[i][kg], aAddr + buf * ABUF + (i * 16 * LDA + kg * 16) * 2);

        #pragma unroll
        for (int kg = 0; kg < 2; kg++) {
            #pragma unroll
            for (int nb = 0; nb < NB16; nb++) {
                uint32_t bb[4];
                ldsm4t(bb, bAddr + buf * BBUF + (kg * 16 * LDB + nb * 16) * 2);
                #pragma unroll
                for (int i = 0; i < 2; i++) {
                    mma_f16(c[i][2 * nb],     af[i][kg], &bb[0]);
                    mma_f16(c[i][2 * nb + 1], af[i][kg], &bb[2]);
                }
            }
        }
    }

    #pragma unroll
    for (int i = 0; i < 2; i++) {
        #pragma unroll
        for (int nb = 0; nb < NB; nb++) {
            int row = m0 + wm + i * 16 + g;
            int col = n0 + wn + nb * 8 + 2 * t;
            float2 bb2 = *(const float2*)&bias[col];
            float o00 = c[i][nb][0] + bb2.x, o01 = c[i][nb][1] + bb2.y;
            float o10 = c[i][nb][2] + bb2.x, o11 = c[i][nb][3] + bb2.y;
            if (HALF_OUT) {
                __half* C = (__half*)Cv;
                *(uint32_t*)&C[(size_t)row * N + col] = packh2(o00, o01);
                *(uint32_t*)&C[(size_t)(row + 8) * N + col] = packh2(o10, o11);
            } else {
                float* C = (float*)Cv;
                float2 v0 = { o00, o01 }, v1 = { o10, o11 };
                *(float2*)&C[(size_t)row * N + col] = v0;
                *(float2*)&C[(size_t)(row + 8) * N + col] = v1;
            }
        }
    }
}

// ---------------- pack GEMM: W_pack[h*128+i][n] = sum_j W_uv[i][h*256+j] * W_o[h*256+j][n]
// grid (8 n-tiles, 1, 8 heads). M=128, N=1024, K=256, BN=128.
__global__ __launch_bounds__(256, 2) void hgemm_pack(
    const __half* __restrict__ wukv, const __half* __restrict__ woh,
    __half* __restrict__ wpack)
{
    constexpr int BM = 128, BK = 32, BN = 128, ST = 3;
    constexpr int LDA = BK + 8;
    constexpr int LDB = BN + 8;
    __shared__ __half As[ST][BM][LDA];
    __shared__ __half Bs[ST][BK][LDB];

    int tid = threadIdx.x, lane = tid & 31, w = tid >> 5;
    int g = lane >> 2, t = lane & 3;
    int wm = (w >> 1) * 32, wn = (w & 1) * 64;
    int n0 = blockIdx.x * BN;
    int z = blockIdx.z;

    int rowX = (lane & 7) + ((lane >> 3) & 1) * 8;
    int colX = (lane >> 4) * 8;

    uint32_t aAddr = (uint32_t)__cvta_generic_to_shared(&As[0][wm + rowX][colX]);
    uint32_t bAddr = (uint32_t)__cvta_generic_to_shared(&Bs[0][rowX][wn + colX]);
    constexpr uint32_t ABUF = BM * LDA * 2;
    constexpr uint32_t BBUF = BK * LDB * 2;

    const __half* Ag = wukv + z * 256;                      // lda = 2048
    const __half* Bg = woh + (size_t)(z * 256) * 1024 + n0; // ldb = 1024

    auto load = [&](int k0, int buf) {
        #pragma unroll
        for (int i = tid; i < BM * BK / 8; i += 256) {
            int r = i >> 2, c = (i & 3) * 8;
            cp_async16(&As[buf][r][c], &Ag[(size_t)r * 2048 + k0 + c]);
        }
        #pragma unroll
        for (int i = tid; i < BK * BN / 8; i += 256) {
            int r = i >> 4, c = (i & 15) * 8;
            cp_async16(&Bs[buf][r][c], &Bg[(size_t)(k0 + r) * 1024 + c]);
        }
    };

    float c[2][8][4] = {};
    load(0, 0); CP_COMMIT();
    load(BK, 1); CP_COMMIT();

    for (int it = 0; it < 8; it++) {
        int buf = it % 3;
        CP_WAIT1();
        __syncthreads();
        if (it + 2 < 8) load((it + 2) * BK, (it + 2) % 3);
        CP_COMMIT();

        uint32_t af[2][2][4];
        #pragma unroll
        for (int i = 0; i < 2; i++)
            #pragma unroll
            for (int kg = 0; kg < 2; kg++)
                ldsm4(af[i][kg], aAddr + buf * ABUF + (i * 16 * LDA + kg * 16) * 2);

        #pragma unroll
        for (int kg = 0; kg < 2; kg++) {
            #pragma unroll
            for (int nb = 0; nb < 4; nb++) {
                uint32_t bb[4];
                ldsm4t(bb, bAddr + buf * BBUF + (kg * 16 * LDB + nb * 16) * 2);
                #pragma unroll
                for (int i = 0; i < 2; i++) {
                    mma_f16(c[i][2 * nb],     af[i][kg], &bb[0]);
                    mma_f16(c[i][2 * nb + 1], af[i][kg], &bb[2]);
                }
            }
        }
    }

    #pragma unroll
    for (int i = 0; i < 2; i++) {
        #pragma unroll
        for (int nb = 0; nb < 8; nb++) {
            int row = z * 128 + wm + i * 16 + g;
            int col = n0 + wn + nb * 8 + 2 * t;
            *(uint32_t*)&wpack[(size_t)row * 1024 + col] = packh2(c[i][nb][0], c[i][nb][1]);
            *(uint32_t*)&wpack[(size_t)(row + 8) * 1024 + col] = packh2(c[i][nb][2], c[i][nb][3]);
        }
    }
}

// ---------------- fused RMSNorm + K-rope ----------------
__global__ __launch_bounds__(128) void norm_rope_kernel(
    const float* __restrict__ dqkv,
    const float* __restrict__ qnw, const float* __restrict__ kvnw,
    const int* __restrict__ pos_ids,
    __half* __restrict__ cq, __half* __restrict__ ckv, float* __restrict__ kr)
{
    int t = blockIdx.x, tid = threadIdx.x;
    int lane = tid & 31, wid = tid >> 5;
    __shared__ float r1[4], r2[4];
    const float* row = dqkv + (size_t)t * 320;
    float v1 = row[tid];
    float v2 = row[128 + tid];
    float s1 = v1 * v1, s2 = v2 * v2;
    #pragma unroll
    for (int o = 16; o; o >>= 1) {
        s1 += __shfl_xor_sync(0xffffffffu, s1, o);
        s2 += __shfl_xor_sync(0xffffffffu, s2, o);
    }
    if (!lane) { r1[wid] = s1; r2[wid] = s2; }
    __syncthreads();
    float t1 = r1[0] + r1[1] + r1[2] + r1[3];
    float t2 = r2[0] + r2[1] + r2[2] + r2[3];
    cq[t * 128 + tid]  = __float2half_rn(qnw[tid]  * v1 * rsqrtf(t1 * (1.0f / 128.0f) + 1e-8f));
    ckv[t * 128 + tid] = __float2half_rn(kvnw[tid] * v2 * rsqrtf(t2 * (1.0f / 128.0f) + 1e-8f));
    if (tid < 64) {
        int p = pos_ids[t];
        int i = tid >> 1;
        float invf = exp2f(-(float)i * KR_EXP);
        float ang = (float)p * invf;
        float sn, cs; sincosf(ang, &sn, &cs);
        float xe = row[256 + 2 * i];
        float xo = row[256 + 2 * i + 1];
        kr[t * 64 + tid] = (tid & 1) ? (xe * sn + xo * cs) : (xe * cs - xo * sn);
    }
}

// ---------------- scatter Q/K ----------------
__global__ __launch_bounds__(256) void scatter_qk(
    const __half* __restrict__ qraw, const __half* __restrict__ knraw,
    const float* __restrict__ kr, const int* __restrict__ pos_ids,
    __half* __restrict__ gq, __half* __restrict__ gk)
{
    int t = blockIdx.x;
    int b = t >> 11, s = t & 2047;
    int tid = threadIdx.x;
    int p = pos_ids[t];
    const __half* qrow = qraw + (size_t)t * 1024;
    const __half* knrow = knraw + (size_t)t * 512;

    float sn = 0.f, cs = 0.f;
    int j = 0, iq = 0;
    if (tid >= 96 && tid < 128) {
        j = tid - 96; iq = j >> 1;
        float invf = exp2f(-(float)iq * QR_EXP);
        float ang = (float)p * invf;
        sincosf(ang, &sn, &cs);
    }

    for (int h = 0; h < 8; h++) {
        size_t qk_base = ((size_t)(b * 8 + h) * 2048 + s) * 128;
        if (tid < 128) {
            int d = tid;
            __half val;
            if (d < 96) {
                val = qrow[h * 96 + d];
            } else {
                const __half* rb = qrow + 768 + h * 32;
                float xe = __half2float(rb[2 * iq]), xo = __half2float(rb[2 * iq + 1]);
                val = __float2half_rn((j & 1) ? (xe * sn + xo * cs) : (xe * cs - xo * sn));
            }
            gq[qk_base + d] = val;
        } else {
            int d = tid - 128;
            gk[qk_base + d] = (d < 64) ? knrow[h * 64 + d]
                                       : __float2half_rn(kr[t * 64 + (d - 64)]);
        }
    }
}

// ---------------- ckvn transpose: [t][128] -> [b][128][2048] ----------------
__global__ __launch_bounds__(256) void ckv_transpose(
    const __half* __restrict__ ckvh, __half* __restrict__ ckvT)
{
    __shared__ __half ts[32][36];
    int s0 = blockIdx.x * 32, d0 = blockIdx.y * 32, b = blockIdx.z;
    int c = threadIdx.x & 31, r0 = threadIdx.x >> 5;
    #pragma unroll
    for (int rr = r0; rr < 32; rr += 8)
        ts[rr][c] = ckvh[(size_t)(b * 2048 + s0 + rr) * 128 + d0 + c];
    __syncthreads();
    #pragma unroll
    for (int rr = r0; rr < 32; rr += 8)
        ckvT[(size_t)(b * 128 + d0 + rr) * 2048 + s0 + c] = ts[c][rr];
}

// ---------------- fp16 flash attention, latent PV (128-dim shared ckvn) ----------
#define LQ 136
#define LK 136
#define LV 72
#define FQ_H (128 * LQ)
#define FK_H (64 * LK)
#define FV_H (128 * LV)
#define FA6_BYTES ((FQ_H + FK_H + FV_H) * 2 + 256)

__global__ __launch_bounds__(256, 1) void flash_f16(
    const __half* __restrict__ Q, const __half* __restrict__ K,
    const __half* __restrict__ CT, __half* __restrict__ O)
{
    extern __shared__ __align__(16) __half smh[];
    __half* Qs = smh;            // [128][136]
    __half* Ks = Qs + FQ_H;      // [64][136]
    __half* Vs = Ks + FK_H;      // [128][72]  (ckvn^T tile: [d][seq64])

    int bh = blockIdx.y, q0 = blockIdx.x * 128;
    const __half* Qg = Q + ((size_t)bh * 2048 + q0) * 128;
    const __half* Kg = K + (size_t)bh * 2048 * 128;
    const __half* Vg = CT + (size_t)(bh >> 3) * 128 * 2048;
    int tid = threadIdx.x, lane = tid & 31, w = tid >> 5;
    int g = lane >> 2, t = lane & 3;
    int wm = w * 16;

    int rowA = (lane & 7) + ((lane >> 3) & 1) * 8;
    int colA = (lane >> 4) * 8;
    int rowB = (lane & 7) + ((lane >> 4) & 1) * 8;
    int colB = ((lane >> 3) & 1) * 8;

    uint32_t qA = (uint32_t)__cvta_generic_to_shared(&Qs[(wm + rowA) * LQ + colA]);
    uint32_t kB = (uint32_t)__cvta_generic_to_shared(&Ks[rowB * LK + colB]);
    uint32_t vB = (uint32_t)__cvta_generic_to_shared(&Vs[rowB * LV + colB]);

    auto loadK = [&](int kc) {
        const __half* Kc = Kg + (size_t)kc * 64 * 128;
        #pragma unroll
        for (int i = tid; i < 1024; i += 256) {
            int r = i >> 4, c = i & 15;
            cp_async16(&Ks[r * LK + c * 8], &Kc[r * 128 + c * 8]);
        }
    };
    auto loadV = [&](int kc) {
        #pragma unroll
        for (int i = tid; i < 1024; i += 256) {
            int r = i >> 3, c = i & 7;
            cp_async16(&Vs[r * LV + c * 8], &Vg[(size_t)r * 2048 + kc * 64 + c * 8]);
        }
    };

    for (int i = tid; i < 2048; i += 256) {
        int r = i >> 4, c = i & 15;
        *(uint4*)&Qs[r * LQ + c * 8] = *(const uint4*)&Qg[r * 128 + c * 8];
    }
    loadK(0); CP_COMMIT();
    loadV(0); CP_COMMIT();
    __syncthreads();

    uint32_t qf[8][4];
    #pragma unroll
    for (int kg = 0; kg < 8; kg++) ldsm4(qf[kg], qA + kg * 32);

    float m0 = -1e30f, m1 = -1e30f, l0 = 0.f, l1 = 0.f;
    float oc[16][4] = {};
    const float scale = 0.08838834764831845f;  // 1/sqrt(128)

    for (int kc = 0; kc < 32; kc++) {
        CP_WAIT1();
        __syncthreads();

        float sc[8][4] = {};
        #pragma unroll
        for (int kg = 0; kg < 8; kg++) {
            #pragma unroll
            for (int ng = 0; ng < 4; ng++) {
                uint32_t bb[4];
                ldsm4(bb, kB + ng * 16 * LK * 2 + kg * 32);
                mma_f16(sc[2 * ng],     qf[kg], &bb[0]);
                mma_f16(sc[2 * ng + 1], qf[kg], &bb[2]);
            }
        }
        __syncthreads();

        float mc0 = -1e30f, mc1 = -1e30f;
        #pragma unroll
        for (int jj = 0; jj < 8; jj++) {
            sc[jj][0] *= scale; sc[jj][1] *= scale;
            sc[jj][2] *= scale; sc[jj][3] *= scale;
            mc0 = fmaxf(mc0, fmaxf(sc[jj][0], sc[jj][1]));
            mc1 = fmaxf(mc1, fmaxf(sc[jj][2], sc[jj][3]));
        }
        mc0 = fmaxf(mc0, __shfl_xor_sync(0xffffffffu, mc0, 1));
        mc0 = fmaxf(mc0, __shfl_xor_sync(0xffffffffu, mc0, 2));
        mc1 = fmaxf(mc1, __shfl_xor_sync(0xffffffffu, mc1, 1));
        mc1 = fmaxf(mc1, __shfl_xor_sync(0xffffffffu, mc1, 2));
        float mn0 = fmaxf(m0, mc0), mn1 = fmaxf(m1, mc1);
        float al0 = __expf(m0 - mn0), al1 = __expf(m1 - mn1);
        m0 = mn0; m1 = mn1;

        uint32_t ph[4][4];
        float ls0 = 0.f, ls1 = 0.f;
        #pragma unroll
        for (int jj = 0; jj < 8; jj++) {
            float e0 = __expf(sc[jj][0] - mn0);
            float e1 = __expf(sc[jj][1] - mn0);
            float e2 = __expf(sc[jj][2] - mn1);
            float e3 = __expf(sc[jj][3] - mn1);
            ls0 += e0 + e1; ls1 += e2 + e3;
            int kg = jj >> 1, hi = (jj & 1) * 2;
            ph[kg][hi]     = packh2(e0, e1);
            ph[kg][hi + 1] = packh2(e2, e3);
        }
        ls0 += __shfl_xor_sync(0xffffffffu, ls0, 1);
        ls0 += __shfl_xor_sync(0xffffffffu, ls0, 2);
        ls1 += __shfl_xor_sync(0xffffffffu, ls1, 1);
        ls1 += __shfl_xor_sync(0xffffffffu, ls1, 2);
        l0 = l0 * al0 + ls0;
        l1 = l1 * al1 + ls1;

        if (kc + 1 < 32) loadK(kc + 1);
        CP_COMMIT();
        CP_WAIT1();
        __syncthreads();

        #pragma unroll
        for (int nt = 0; nt < 16; nt++) {
            oc[nt][0] *= al0; oc[nt][1] *= al0;
            oc[nt][2] *= al1; oc[nt][3] *= al1;
        }
        #pragma unroll
        for (int kg = 0; kg < 4; kg++) {
            #pragma unroll
            for (int ng = 0; ng < 8; ng++) {
                uint32_t bb[4];
                ldsm4(bb, vB + ng * 16 * LV * 2 + kg * 32);
                mma_f16(oc[2 * ng],     ph[kg], &bb[0]);
                mma_f16(oc[2 * ng + 1], ph[kg], &bb[2]);
            }
        }
        __syncthreads();
        if (kc + 1 < 32) loadV(kc + 1);
        CP_COMMIT();
    }

    // epilogue -> latent [t][h*128 + d] fp16
    int b = bh >> 3, h = bh & 7;
    float inv0 = 1.0f / l0, inv1 = 1.0f / l1;
    int row0 = q0 + wm + g, row1 = row0 + 8;
    #pragma unroll
    for (int nt = 0; nt < 16; nt++) {
        int col = h * 128 + nt * 8 + 2 * t;
        uint32_t p0 = packh2(oc[nt][0] * inv0, oc[nt][1] * inv0);
        uint32_t p1 = packh2(oc[nt][2] * inv1, oc[nt][3] * inv1);
        *(uint32_t*)&O[((size_t)(b * 2048 + row0)) * 1024 + col] = p0;
        *(uint32_t*)&O[((size_t)(b * 2048 + row1)) * 1024 + col] = p1;
    }
}

// ---------------- launch ----------------
extern "C" void kernel_launch(void* const* d_in, const int* in_sizes, int n_in,
                              void* d_out, int out_size)
{
    const float* x         = (const float*)d_in[0];
    const int*   pos       = (const int*)d_in[1];
    const float* w_dq_w    = (const float*)d_in[2];
    const float* w_dq_b    = (const float*)d_in[3];
    const float* q_norm_w  = (const float*)d_in[4];
    const float* w_uq_qr_w = (const float*)d_in[5];
    const float* w_uq_qr_b = (const float*)d_in[6];
    const float* w_dkv_w   = (const float*)d_in[7];
    const float* w_dkv_b   = (const float*)d_in[8];
    const float* kv_norm_w = (const float*)d_in[9];
    const float* w_uk_w    = (const float*)d_in[10];
    const float* w_uk_b    = (const float*)d_in[11];
    const float* w_o_w     = (const float*)d_in[12];
    const float* w_o_b     = (const float*)d_in[13];
    float* out = (float*)d_out;

    float *dqkv, *kr, *bqkv, *beff;
    __half *xh, *wqkv, *wuq, *wukn, *wukv, *woh, *wpack, *cqh, *ckvh, *ckvT;
    __half *qrawh, *knh, *gq, *gk, *lath;
    cudaGetSymbolAddress((void**)&dqkv, g_dqkv);
    cudaGetSymbolAddress((void**)&kr, g_krope);
    cudaGetSymbolAddress((void**)&bqkv, g_bqkv);
    cudaGetSymbolAddress((void**)&beff, g_beff);
    cudaGetSymbolAddress((void**)&qrawh, g_qrawh);
    cudaGetSymbolAddress((void**)&knh, g_knh);
    cudaGetSymbolAddress((void**)&xh, g_xh);
    cudaGetSymbolAddress((void**)&wqkv, g_wqkv);
    cudaGetSymbolAddress((void**)&wuq, g_wuq);
    cudaGetSymbolAddress((void**)&wukn, g_wukn);
    cudaGetSymbolAddress((void**)&wukv, g_wukv);
    cudaGetSymbolAddress((void**)&woh, g_woh);
    cudaGetSymbolAddress((void**)&wpack, g_wpack);
    cudaGetSymbolAddress((void**)&cqh, g_cqh);
    cudaGetSymbolAddress((void**)&ckvh, g_ckvh);
    cudaGetSymbolAddress((void**)&ckvT, g_ckvT);
    cudaGetSymbolAddress((void**)&gq, g_qh);
    cudaGetSymbolAddress((void**)&gk, g_kh);
    cudaGetSymbolAddress((void**)&lath, g_lath);

    cudaFuncSetAttribute(flash_f16, cudaFuncAttributeMaxDynamicSharedMemorySize,
                         FA6_BYTES);

    // conversions + packed-weight precompute
    convert_all<<<(CV_QUADS + 255) / 256, 256>>>(
        x, w_dq_w, w_dkv_w, w_uq_qr_w, w_uk_w, w_o_w, w_dq_b, w_dkv_b,
        xh, wqkv, wuq, wukn, wukv, woh, bqkv);
    beff_kernel<<<4, 256>>>(w_o_w, w_uk_b, w_o_b, beff);
    hgemm_pack<<<dim3(8, 1, 8), 256>>>(wukv, woh, wpack);

    // fused down projection
    hgemm<64, false><<<dim3(5, 32), 256>>>(xh, wqkv, bqkv, dqkv, T_TOK, 320, DIMM);
    // rmsnorm + k rope
    norm_rope_kernel<<<T_TOK, 128>>>(dqkv, q_norm_w, kv_norm_w, pos, cqh, ckvh, kr);
    // up projections (q full; kv -> k_nope only)
    hgemm<128, true><<<dim3(8, 32), 256>>>(cqh, wuq, w_uq_qr_b, qrawh, T_TOK, 1024, QC);
    hgemm<128, true><<<dim3(4, 32), 256>>>(ckvh, wukn, w_uk_b, knh, T_TOK, 512, KVC);
    // build per-head states + latent transpose
    scatter_qk<<<T_TOK, 256>>>(qrawh, knh, kr, pos, gq, gk);
    ckv_transpose<<<dim3(64, 4, 2), 256>>>(ckvh, ckvT);
    // attention in latent space
    flash_f16<<<dim3(S_LEN / 128, 16), 256, FA6_BYTES>>>(gq, gk, ckvT, lath);
    // absorbed output projection
    hgemm<128, false><<<dim3(8, 32), 256>>>(lath, wpack, beff, out, T_TOK, DIMM, 1024);
}

// round 17
// speedup vs baseline: 1.9107x; 1.9107x over previous
#include <cuda_runtime.h>
#include <cuda_fp16.h>
#include <math.h>
#include <stdint.h>

// ---------------- problem constants ----------------
#define T_TOK 4096
#define S_LEN 2048
#define DIMM 1024
#define QC 128
#define KVC 128
#define KROPE 64
#define HD 128

// log2(10000) = 13.287712379549449
#define QR_EXP 0.8304820237218406f   // /16  (q rope, head_dim 32)
#define KR_EXP 0.4152410118609203f   // /32  (k rope, head_dim 64)

// ---------------- scratch ----------------
__device__ float  g_dqkv[(size_t)T_TOK * 320];
__device__ float  g_krope[T_TOK * KROPE];
__device__ __half g_qrawh[(size_t)T_TOK * 1024];
__device__ __half g_knh[(size_t)T_TOK * 512];        // k_nope up-proj out
__device__ __half g_xh[(size_t)T_TOK * DIMM];
__device__ __half g_wqkv[DIMM * 320];
__device__ float  g_bqkv[320];
__device__ __half g_wuq[QC * 1024];
__device__ __half g_wukn[KVC * 512];                 // W_uk (k_nope cols)
__device__ __half g_wukv[KVC * 2048];                // W_uv (v cols)
__device__ __half g_woh[(size_t)2048 * DIMM];        // W_o fp16 [k][n]
__device__ __half g_wpack[(size_t)1024 * 1024];      // packed W_uv@W_o
__device__ float  g_beff[1024];                      // b_o + b_v @ W_o
__device__ float  g_beff_part[16 * 1024];
__device__ __half g_cqh[T_TOK * QC];
__device__ __half g_ckvh[T_TOK * KVC];
__device__ __half g_ckvT[(size_t)2 * KVC * S_LEN];   // [b][128][2048] (ckvn^T)
__device__ __half g_qh[(size_t)16 * S_LEN * HD];
__device__ __half g_kh[(size_t)16 * S_LEN * HD];
__device__ __half g_lath[(size_t)T_TOK * 1024];      // latent attn out [t][h*128+d]

// ---------------- helpers ----------------
__device__ __forceinline__ void mma_f16(float c[4], const uint32_t a[4], const uint32_t b[2]) {
    asm volatile(
        "mma.sync.aligned.m16n8k16.row.col.f32.f16.f16.f32 "
        "{%0,%1,%2,%3},{%4,%5,%6,%7},{%8,%9},{%0,%1,%2,%3};"
        : "+f"(c[0]), "+f"(c[1]), "+f"(c[2]), "+f"(c[3])
        : "r"(a[0]), "r"(a[1]), "r"(a[2]), "r"(a[3]), "r"(b[0]), "r"(b[1]));
}

__device__ __forceinline__ void ldsm4(uint32_t r[4], uint32_t saddr) {
    asm volatile("ldmatrix.sync.aligned.m8n8.x4.shared.b16 {%0,%1,%2,%3}, [%4];"
        : "=r"(r[0]), "=r"(r[1]), "=r"(r[2]), "=r"(r[3]) : "r"(saddr));
}
__device__ __forceinline__ void ldsm4t(uint32_t r[4], uint32_t saddr) {
    asm volatile("ldmatrix.sync.aligned.m8n8.x4.trans.shared.b16 {%0,%1,%2,%3}, [%4];"
        : "=r"(r[0]), "=r"(r[1]), "=r"(r[2]), "=r"(r[3]) : "r"(saddr));
}

__device__ __forceinline__ void cp_async16(void* smem_dst, const void* gsrc) {
    uint32_t s = (uint32_t)__cvta_generic_to_shared(smem_dst);
    asm volatile("cp.async.ca.shared.global [%0], [%1], 16;\n" :: "r"(s), "l"(gsrc));
}
#define CP_COMMIT() asm volatile("cp.async.commit_group;\n" ::: "memory")
#define CP_WAIT1()  asm volatile("cp.async.wait_group 1;\n" ::: "memory")

__device__ __forceinline__ uint32_t packh2(float lo, float hi) {
    __half2 h = __floats2half2_rn(lo, hi);
    return *(uint32_t*)&h;
}

// ---------------- fused f32 -> f16 conversion ----------------
#define CV_X   (T_TOK * DIMM)
#define CV_DQ  (DIMM * QC)
#define CV_DKV (DIMM * 192)
#define CV_UQ  (QC * 1024)
#define CV_UK  (KVC * 2560)
#define CV_WO  (2048 * DIMM)
#define CV_TOTAL (CV_X + CV_DQ + CV_DKV + CV_UQ + CV_UK + CV_WO)
#define CV_QUADS (CV_TOTAL / 4)

__global__ __launch_bounds__(256) void convert_all(
    const float* __restrict__ x,   const float* __restrict__ wdq,
    const float* __restrict__ wdkv,const float* __restrict__ wuq,
    const float* __restrict__ wuk, const float* __restrict__ wo,
    const float* __restrict__ bdq, const float* __restrict__ bdkv,
    __half* __restrict__ xh,   __half* __restrict__ wqkvh,
    __half* __restrict__ wuqh, __half* __restrict__ wuknh,
    __half* __restrict__ wukvh,__half* __restrict__ woh,
    float* __restrict__ bqkv)
{
    if (blockIdx.x == 0) {
        int tix = threadIdx.x;
        if (tix < 320) bqkv[tix] = (tix < 128) ? bdq[tix] : bdkv[tix - 128];
        if (tix < 64)  bqkv[256 + tix] = bdkv[128 + tix];
    }
    long long i = ((long long)blockIdx.x * 256 + threadIdx.x) * 4;
    if (i >= CV_TOTAL) return;
    long long off = i;
    const float* src;
    __half* dst;
    long long didx;
    if (off < CV_X) {
        src = x; dst = xh; didx = off;
    } else if ((off -= CV_X) < CV_DQ) {
        src = wdq; dst = wqkvh;
        didx = (off >> 7) * 320 + (off & 127);
    } else if ((off -= CV_DQ) < CV_DKV) {
        src = wdkv; dst = wqkvh;
        didx = (off / 192) * 320 + 128 + (off % 192);
    } else if ((off -= CV_DKV) < CV_UQ) {
        src = wuq; dst = wuqh; didx = off;
    } else if ((off -= CV_UQ) < CV_UK) {
        src = wuk;
        long long row = off / 2560, col = off % 2560;
        if (col < 512) { dst = wuknh; didx = row * 512 + col; }
        else           { dst = wukvh; didx = row * 2048 + (col - 512); }
    } else {
        off -= CV_UK; src = wo; dst = woh; didx = off;
    }
    float4 v = *(const float4*)&src[off];
    *(__half2*)&dst[didx]     = __floats2half2_rn(v.x, v.y);
    *(__half2*)&dst[didx + 2] = __floats2half2_rn(v.z, v.w);
}

// ---------------- b_eff = w_o_b + b_v @ W_o  (two-stage parallel) ----------------
__global__ __launch_bounds__(256) void beff_part_kernel(
    const float* __restrict__ wo, const float* __restrict__ bukuv,
    float* __restrict__ part)
{
    __shared__ float sm[256];
    int n = blockIdx.x * 128 + (threadIdx.x & 127);
    int kt = threadIdx.x >> 7;            // 0..1
    int kb = blockIdx.y;                  // 0..15
    float acc = 0.f;
    #pragma unroll 8
    for (int j = 0; j < 64; j++) {
        int k = kb * 128 + kt * 64 + j;
        acc += bukuv[512 + k] * wo[(size_t)k * 1024 + n];
    }
    sm[threadIdx.x] = acc;
    __syncthreads();
    if (kt == 0) part[kb * 1024 + n] = sm[threadIdx.x] + sm[threadIdx.x + 128];
}

__global__ __launch_bounds__(256) void beff_reduce_kernel(
    const float* __restrict__ part, const float* __restrict__ bo,
    float* __restrict__ beff)
{
    int n = blockIdx.x * 256 + threadIdx.x;
    float acc = bo[n];
    #pragma unroll
    for (int kb = 0; kb < 16; kb++) acc += part[kb * 1024 + n];
    beff[n] = acc;
}

// ---------------- fp16 tensor-core GEMM, 3-stage cp.async pipeline ----------------
template<int BN, bool HALF_OUT>
__global__ __launch_bounds__(256, 2) void hgemm(
    const __half* __restrict__ A, const __half* __restrict__ W,
    const float* __restrict__ bias, void* __restrict__ Cv,
    int M, int N, int K)
{
    constexpr int BM = 128, BK = 32, ST = 3;
    constexpr int LDA = BK + 8;
    constexpr int LDB = BN + 8;
    constexpr int WN = BN / 2;
    constexpr int NB = WN / 8;
    constexpr int NB16 = WN / 16;
    __shared__ __half As[ST][BM][LDA];
    __shared__ __half Bs[ST][BK][LDB];

    int tid = threadIdx.x, lane = tid & 31, w = tid >> 5;
    int g = lane >> 2, t = lane & 3;
    int wm = (w >> 1) * 32, wn = (w & 1) * WN;
    int m0 = blockIdx.y * BM, n0 = blockIdx.x * BN;

    int rowX = (lane & 7) + ((lane >> 3) & 1) * 8;
    int colX = (lane >> 4) * 8;

    uint32_t aAddr = (uint32_t)__cvta_generic_to_shared(&As[0][wm + rowX][colX]);
    uint32_t bAddr = (uint32_t)__cvta_generic_to_shared(&Bs[0][rowX][wn + colX]);
    constexpr uint32_t ABUF = BM * LDA * 2;
    constexpr uint32_t BBUF = BK * LDB * 2;

    const __half* Ag = A + (size_t)m0 * K;
    const __half* Wg = W + n0;

    auto load = [&](int k0, int buf) {
        #pragma unroll
        for (int i = tid; i < BM * BK / 8; i += 256) {
            int r = i >> 2, c = (i & 3) * 8;
            cp_async16(&As[buf][r][c], &Ag[(size_t)r * K + k0 + c]);
        }
        #pragma unroll
        for (int i = tid; i < BK * BN / 8; i += 256) {
            int r = i / (BN / 8), c = (i % (BN / 8)) * 8;
            cp_async16(&Bs[buf][r][c], &Wg[(size_t)(k0 + r) * N + c]);
        }
    };

    float c[2][NB][4] = {};

    int nt = K / BK;
    load(0, 0); CP_COMMIT();
    load(BK, 1); CP_COMMIT();

    for (int it = 0; it < nt; it++) {
        int buf = it % 3;
        CP_WAIT1();
        __syncthreads();
        if (it + 2 < nt) load((it + 2) * BK, (it + 2) % 3);
        CP_COMMIT();

        uint32_t af[2][2][4];
        #pragma unroll
        for (int i = 0; i < 2; i++)
            #pragma unroll
            for (int kg = 0; kg < 2; kg++)
                ldsm4(af[i][kg], aAddr + buf * ABUF + (i * 16 * LDA + kg * 16) * 2);

        #pragma unroll
        for (int kg = 0; kg < 2; kg++) {
            #pragma unroll
            for (int nb = 0; nb < NB16; nb++) {
                uint32_t bb[4];
                ldsm4t(bb, bAddr + buf * BBUF + (kg * 16 * LDB + nb * 16) * 2);
                #pragma unroll
                for (int i = 0; i < 2; i++) {
                    mma_f16(c[i][2 * nb],     af[i][kg], &bb[0]);
                    mma_f16(c[i][2 * nb + 1], af[i][kg], &bb[2]);
                }
            }
        }
    }

    #pragma unroll
    for (int i = 0; i < 2; i++) {
        #pragma unroll
        for (int nb = 0; nb < NB; nb++) {
            int row = m0 + wm + i * 16 + g;
            int col = n0 + wn + nb * 8 + 2 * t;
            float2 bb2 = *(const float2*)&bias[col];
            float o00 = c[i][nb][0] + bb2.x, o01 = c[i][nb][1] + bb2.y;
            float o10 = c[i][nb][2] + bb2.x, o11 = c[i][nb][3] + bb2.y;
            if (HALF_OUT) {
                __half* C = (__half*)Cv;
                *(uint32_t*)&C[(size_t)row * N + col] = packh2(o00, o01);
                *(uint32_t*)&C[(size_t)(row + 8) * N + col] = packh2(o10, o11);
            } else {
                float* C = (float*)Cv;
                float2 v0 = { o00, o01 }, v1 = { o10, o11 };
                *(float2*)&C[(size_t)row * N + col] = v0;
                *(float2*)&C[(size_t)(row + 8) * N + col] = v1;
            }
        }
    }
}

// ---------------- pack GEMM: W_pack = blockdiag(W_uv_h) @ W_o ----------------
__global__ __launch_bounds__(256, 2) void hgemm_pack(
    const __half* __restrict__ wukv, const __half* __restrict__ woh,
    __half* __restrict__ wpack)
{
    constexpr int BM = 128, BK = 32, BN = 128, ST = 3;
    constexpr int LDA = BK + 8;
    constexpr int LDB = BN + 8;
    __shared__ __half As[ST][BM][LDA];
    __shared__ __half Bs[ST][BK][LDB];

    int tid = threadIdx.x, lane = tid & 31, w = tid >> 5;
    int g = lane >> 2, t = lane & 3;
    int wm = (w >> 1) * 32, wn = (w & 1) * 64;
    int n0 = blockIdx.x * BN;
    int z = blockIdx.z;

    int rowX = (lane & 7) + ((lane >> 3) & 1) * 8;
    int colX = (lane >> 4) * 8;

    uint32_t aAddr = (uint32_t)__cvta_generic_to_shared(&As[0][wm + rowX][colX]);
    uint32_t bAddr = (uint32_t)__cvta_generic_to_shared(&Bs[0][rowX][wn + colX]);
    constexpr uint32_t ABUF = BM * LDA * 2;
    constexpr uint32_t BBUF = BK * LDB * 2;

    const __half* Ag = wukv + z * 256;                      // lda = 2048
    const __half* Bg = woh + (size_t)(z * 256) * 1024 + n0; // ldb = 1024

    auto load = [&](int k0, int buf) {
        #pragma unroll
        for (int i = tid; i < BM * BK / 8; i += 256) {
            int r = i >> 2, c = (i & 3) * 8;
            cp_async16(&As[buf][r][c], &Ag[(size_t)r * 2048 + k0 + c]);
        }
        #pragma unroll
        for (int i = tid; i < BK * BN / 8; i += 256) {
            int r = i >> 4, c = (i & 15) * 8;
            cp_async16(&Bs[buf][r][c], &Bg[(size_t)(k0 + r) * 1024 + c]);
        }
    };

    float c[2][8][4] = {};
    load(0, 0); CP_COMMIT();
    load(BK, 1); CP_COMMIT();

    for (int it = 0; it < 8; it++) {
        int buf = it % 3;
        CP_WAIT1();
        __syncthreads();
        if (it + 2 < 8) load((it + 2) * BK, (it + 2) % 3);
        CP_COMMIT();

        uint32_t af[2][2][4];
        #pragma unroll
        for (int i = 0; i < 2; i++)
            #pragma unroll
            for (int kg = 0; kg < 2; kg++)
                ldsm4(af[i][kg], aAddr + buf * ABUF + (i * 16 * LDA + kg * 16) * 2);

        #pragma unroll
        for (int kg = 0; kg < 2; kg++) {
            #pragma unroll
            for (int nb = 0; nb < 4; nb++) {
                uint32_t bb[4];
                ldsm4t(bb, bAddr + buf * BBUF + (kg * 16 * LDB + nb * 16) * 2);
                #pragma unroll
                for (int i = 0; i < 2; i++) {
                    mma_f16(c[i][2 * nb],     af[i][kg], &bb[0]);
                    mma_f16(c[i][2 * nb + 1], af[i][kg], &bb[2]);
                }
            }
        }
    }

    #pragma unroll
    for (int i = 0; i < 2; i++) {
        #pragma unroll
        for (int nb = 0; nb < 8; nb++) {
            int row = z * 128 + wm + i * 16 + g;
            int col = n0 + wn + nb * 8 + 2 * t;
            *(uint32_t*)&wpack[(size_t)row * 1024 + col] = packh2(c[i][nb][0], c[i][nb][1]);
            *(uint32_t*)&wpack[(size_t)(row + 8) * 1024 + col] = packh2(c[i][nb][2], c[i][nb][3]);
        }
    }
}

// ---------------- fused RMSNorm + K-rope ----------------
__global__ __launch_bounds__(128) void norm_rope_kernel(
    const float* __restrict__ dqkv,
    const float* __restrict__ qnw, const float* __restrict__ kvnw,
    const int* __restrict__ pos_ids,
    __half* __restrict__ cq, __half* __restrict__ ckv, float* __restrict__ kr)
{
    int t = blockIdx.x, tid = threadIdx.x;
    int lane = tid & 31, wid = tid >> 5;
    __shared__ float r1[4], r2[4];
    const float* row = dqkv + (size_t)t * 320;
    float v1 = row[tid];
    float v2 = row[128 + tid];
    float s1 = v1 * v1, s2 = v2 * v2;
    #pragma unroll
    for (int o = 16; o; o >>= 1) {
        s1 += __shfl_xor_sync(0xffffffffu, s1, o);
        s2 += __shfl_xor_sync(0xffffffffu, s2, o);
    }
    if (!lane) { r1[wid] = s1; r2[wid] = s2; }
    __syncthreads();
    float t1 = r1[0] + r1[1] + r1[2] + r1[3];
    float t2 = r2[0] + r2[1] + r2[2] + r2[3];
    cq[t * 128 + tid]  = __float2half_rn(qnw[tid]  * v1 * rsqrtf(t1 * (1.0f / 128.0f) + 1e-8f));
    ckv[t * 128 + tid] = __float2half_rn(kvnw[tid] * v2 * rsqrtf(t2 * (1.0f / 128.0f) + 1e-8f));
    if (tid < 64) {
        int p = pos_ids[t];
        int i = tid >> 1;
        float invf = exp2f(-(float)i * KR_EXP);
        float ang = (float)p * invf;
        float sn, cs; sincosf(ang, &sn, &cs);
        float xe = row[256 + 2 * i];
        float xo = row[256 + 2 * i + 1];
        kr[t * 64 + tid] = (tid & 1) ? (xe * sn + xo * cs) : (xe * cs - xo * sn);
    }
}

// ---------------- scatter Q/K ----------------
__global__ __launch_bounds__(256) void scatter_qk(
    const __half* __restrict__ qraw, const __half* __restrict__ knraw,
    const float* __restrict__ kr, const int* __restrict__ pos_ids,
    __half* __restrict__ gq, __half* __restrict__ gk)
{
    int t = blockIdx.x;
    int b = t >> 11, s = t & 2047;
    int tid = threadIdx.x;
    int p = pos_ids[t];
    const __half* qrow = qraw + (size_t)t * 1024;
    const __half* knrow = knraw + (size_t)t * 512;

    float sn = 0.f, cs = 0.f;
    int j = 0, iq = 0;
    if (tid >= 96 && tid < 128) {
        j = tid - 96; iq = j >> 1;
        float invf = exp2f(-(float)iq * QR_EXP);
        float ang = (float)p * invf;
        sincosf(ang, &sn, &cs);
    }

    for (int h = 0; h < 8; h++) {
        size_t qk_base = ((size_t)(b * 8 + h) * 2048 + s) * 128;
        if (tid < 128) {
            int d = tid;
            __half val;
            if (d < 96) {
                val = qrow[h * 96 + d];
            } else {
                const __half* rb = qrow + 768 + h * 32;
                float xe = __half2float(rb[2 * iq]), xo = __half2float(rb[2 * iq + 1]);
                val = __float2half_rn((j & 1) ? (xe * sn + xo * cs) : (xe * cs - xo * sn));
            }
            gq[qk_base + d] = val;
        } else {
            int d = tid - 128;
            gk[qk_base + d] = (d < 64) ? knrow[h * 64 + d]
                                       : __float2half_rn(kr[t * 64 + (d - 64)]);
        }
    }
}

// ---------------- ckvn transpose: [t][128] -> [b][128][2048] ----------------
__global__ __launch_bounds__(256) void ckv_transpose(
    const __half* __restrict__ ckvh, __half* __restrict__ ckvT)
{
    __shared__ __half ts[32][36];
    int s0 = blockIdx.x * 32, d0 = blockIdx.y * 32, b = blockIdx.z;
    int c = threadIdx.x & 31, r0 = threadIdx.x >> 5;
    #pragma unroll
    for (int rr = r0; rr < 32; rr += 8)
        ts[rr][c] = ckvh[(size_t)(b * 2048 + s0 + rr) * 128 + d0 + c];
    __syncthreads();
    #pragma unroll
    for (int rr = r0; rr < 32; rr += 8)
        ckvT[(size_t)(b * 128 + d0 + rr) * 2048 + s0 + c] = ts[c][rr];
}

// ---------------- fp16 flash attention, latent PV (128-dim shared ckvn) ----------
#define LQ 136
#define LK 136
#define LV 72
#define FQ_H (128 * LQ)
#define FK_H (64 * LK)
#define FV_H (128 * LV)
#define FA6_BYTES ((FQ_H + FK_H + FV_H) * 2 + 256)

__global__ __launch_bounds__(256, 1) void flash_f16(
    const __half* __restrict__ Q, const __half* __restrict__ K,
    const __half* __restrict__ CT, __half* __restrict__ O)
{
    extern __shared__ __align__(16) __half smh[];
    __half* Qs = smh;            // [128][136]
    __half* Ks = Qs + FQ_H;      // [64][136]
    __half* Vs = Ks + FK_H;      // [128][72]  (ckvn^T tile: [d][seq64])

    int bh = blockIdx.y, q0 = blockIdx.x * 128;
    const __half* Qg = Q + ((size_t)bh * 2048 + q0) * 128;
    const __half* Kg = K + (size_t)bh * 2048 * 128;
    const __half* Vg = CT + (size_t)(bh >> 3) * 128 * 2048;
    int tid = threadIdx.x, lane = tid & 31, w = tid >> 5;
    int g = lane >> 2, t = lane & 3;
    int wm = w * 16;

    int rowA = (lane & 7) + ((lane >> 3) & 1) * 8;
    int colA = (lane >> 4) * 8;
    int rowB = (lane & 7) + ((lane >> 4) & 1) * 8;
    int colB = ((lane >> 3) & 1) * 8;

    uint32_t qA = (uint32_t)__cvta_generic_to_shared(&Qs[(wm + rowA) * LQ + colA]);
    uint32_t kB = (uint32_t)__cvta_generic_to_shared(&Ks[rowB * LK + colB]);
    uint32_t vB = (uint32_t)__cvta_generic_to_shared(&Vs[rowB * LV + colB]);

    auto loadK = [&](int kc) {
        const __half* Kc = Kg + (size_t)kc * 64 * 128;
        #pragma unroll
        for (int i = tid; i < 1024; i += 256) {
            int r = i >> 4, c = i & 15;
            cp_async16(&Ks[r * LK + c * 8], &Kc[r * 128 + c * 8]);
        }
    };
    auto loadV = [&](int kc) {
        #pragma unroll
        for (int i = tid; i < 1024; i += 256) {
            int r = i >> 3, c = i & 7;
            cp_async16(&Vs[r * LV + c * 8], &Vg[(size_t)r * 2048 + kc * 64 + c * 8]);
        }
    };

    for (int i = tid; i < 2048; i += 256) {
        int r = i >> 4, c = i & 15;
        *(uint4*)&Qs[r * LQ + c * 8] = *(const uint4*)&Qg[r * 128 + c * 8];
    }
    loadK(0); CP_COMMIT();
    loadV(0); CP_COMMIT();
    __syncthreads();

    uint32_t qf[8][4];
    #pragma unroll
    for (int kg = 0; kg < 8; kg++) ldsm4(qf[kg], qA + kg * 32);

    float m0 = -1e30f, m1 = -1e30f, l0 = 0.f, l1 = 0.f;
    float oc[16][4] = {};
    const float scale = 0.08838834764831845f;  // 1/sqrt(128)

    for (int kc = 0; kc < 32; kc++) {
        CP_WAIT1();
        __syncthreads();

        float sc[8][4] = {};
        #pragma unroll
        for (int kg = 0; kg < 8; kg++) {
            #pragma unroll
            for (int ng = 0; ng < 4; ng++) {
                uint32_t bb[4];
                ldsm4(bb, kB + ng * 16 * LK * 2 + kg * 32);
                mma_f16(sc[2 * ng],     qf[kg], &bb[0]);
                mma_f16(sc[2 * ng + 1], qf[kg], &bb[2]);
            }
        }
        __syncthreads();

        float mc0 = -1e30f, mc1 = -1e30f;
        #pragma unroll
        for (int jj = 0; jj < 8; jj++) {
            sc[jj][0] *= scale; sc[jj][1] *= scale;
            sc[jj][2] *= scale; sc[jj][3] *= scale;
            mc0 = fmaxf(mc0, fmaxf(sc[jj][0], sc[jj][1]));
            mc1 = fmaxf(mc1, fmaxf(sc[jj][2], sc[jj][3]));
        }
        mc0 = fmaxf(mc0, __shfl_xor_sync(0xffffffffu, mc0, 1));
        mc0 = fmaxf(mc0, __shfl_xor_sync(0xffffffffu, mc0, 2));
        mc1 = fmaxf(mc1, __shfl_xor_sync(0xffffffffu, mc1, 1));
        mc1 = fmaxf(mc1, __shfl_xor_sync(0xffffffffu, mc1, 2));
        float mn0 = fmaxf(m0, mc0), mn1 = fmaxf(m1, mc1);
        float al0 = __expf(m0 - mn0), al1 = __expf(m1 - mn1);
        m0 = mn0; m1 = mn1;

        uint32_t ph[4][4];
        float ls0 = 0.f, ls1 = 0.f;
        #pragma unroll
        for (int jj = 0; jj < 8; jj++) {
            float e0 = __expf(sc[jj][0] - mn0);
            float e1 = __expf(sc[jj][1] - mn0);
            float e2 = __expf(sc[jj][2] - mn1);
            float e3 = __expf(sc[jj][3] - mn1);
            ls0 += e0 + e1; ls1 += e2 + e3;
            int kg = jj >> 1, hi = (jj & 1) * 2;
            ph[kg][hi]     = packh2(e0, e1);
            ph[kg][hi + 1] = packh2(e2, e3);
        }
        ls0 += __shfl_xor_sync(0xffffffffu, ls0, 1);
        ls0 += __shfl_xor_sync(0xffffffffu, ls0, 2);
        ls1 += __shfl_xor_sync(0xffffffffu, ls1, 1);
        ls1 += __shfl_xor_sync(0xffffffffu, ls1, 2);
        l0 = l0 * al0 + ls0;
        l1 = l1 * al1 + ls1;

        if (kc + 1 < 32) loadK(kc + 1);
        CP_COMMIT();
        CP_WAIT1();
        __syncthreads();

        #pragma unroll
        for (int nt = 0; nt < 16; nt++) {
            oc[nt][0] *= al0; oc[nt][1] *= al0;
            oc[nt][2] *= al1; oc[nt][3] *= al1;
        }
        #pragma unroll
        for (int kg = 0; kg < 4; kg++) {
            #pragma unroll
            for (int ng = 0; ng < 8; ng++) {
                uint32_t bb[4];
                ldsm4(bb, vB + ng * 16 * LV * 2 + kg * 32);
                mma_f16(oc[2 * ng],     ph[kg], &bb[0]);
                mma_f16(oc[2 * ng + 1], ph[kg], &bb[2]);
            }
        }
        __syncthreads();
        if (kc + 1 < 32) loadV(kc + 1);
        CP_COMMIT();
    }

    // epilogue -> latent [t][h*128 + d] fp16
    int b = bh >> 3, h = bh & 7;
    float inv0 = 1.0f / l0, inv1 = 1.0f / l1;
    int row0 = q0 + wm + g, row1 = row0 + 8;
    #pragma unroll
    for (int nt = 0; nt < 16; nt++) {
        int col = h * 128 + nt * 8 + 2 * t;
        uint32_t p0 = packh2(oc[nt][0] * inv0, oc[nt][1] * inv0);
        uint32_t p1 = packh2(oc[nt][2] * inv1, oc[nt][3] * inv1);
        *(uint32_t*)&O[((size_t)(b * 2048 + row0)) * 1024 + col] = p0;
        *(uint32_t*)&O[((size_t)(b * 2048 + row1)) * 1024 + col] = p1;
    }
}

// ---------------- launch ----------------
extern "C" void kernel_launch(void* const* d_in, const int* in_sizes, int n_in,
                              void* d_out, int out_size)
{
    const float* x         = (const float*)d_in[0];
    const int*   pos       = (const int*)d_in[1];
    const float* w_dq_w    = (const float*)d_in[2];
    const float* w_dq_b    = (const float*)d_in[3];
    const float* q_norm_w  = (const float*)d_in[4];
    const float* w_uq_qr_w = (const float*)d_in[5];
    const float* w_uq_qr_b = (const float*)d_in[6];
    const float* w_dkv_w   = (const float*)d_in[7];
    const float* w_dkv_b   = (const float*)d_in[8];
    const float* kv_norm_w = (const float*)d_in[9];
    const float* w_uk_w    = (const float*)d_in[10];
    const float* w_uk_b    = (const float*)d_in[11];
    const float* w_o_w     = (const float*)d_in[12];
    const float* w_o_b     = (const float*)d_in[13];
    float* out = (float*)d_out;

    float *dqkv, *kr, *bqkv, *beff, *beffp;
    __half *xh, *wqkv, *wuq, *wukn, *wukv, *woh, *wpack, *cqh, *ckvh, *ckvT;
    __half *qrawh, *knh, *gq, *gk, *lath;
    cudaGetSymbolAddress((void**)&dqkv, g_dqkv);
    cudaGetSymbolAddress((void**)&kr, g_krope);
    cudaGetSymbolAddress((void**)&bqkv, g_bqkv);
    cudaGetSymbolAddress((void**)&beff, g_beff);
    cudaGetSymbolAddress((void**)&beffp, g_beff_part);
    cudaGetSymbolAddress((void**)&qrawh, g_qrawh);
    cudaGetSymbolAddress((void**)&knh, g_knh);
    cudaGetSymbolAddress((void**)&xh, g_xh);
    cudaGetSymbolAddress((void**)&wqkv, g_wqkv);
    cudaGetSymbolAddress((void**)&wuq, g_wuq);
    cudaGetSymbolAddress((void**)&wukn, g_wukn);
    cudaGetSymbolAddress((void**)&wukv, g_wukv);
    cudaGetSymbolAddress((void**)&woh, g_woh);
    cudaGetSymbolAddress((void**)&wpack, g_wpack);
    cudaGetSymbolAddress((void**)&cqh, g_cqh);
    cudaGetSymbolAddress((void**)&ckvh, g_ckvh);
    cudaGetSymbolAddress((void**)&ckvT, g_ckvT);
    cudaGetSymbolAddress((void**)&gq, g_qh);
    cudaGetSymbolAddress((void**)&gk, g_kh);
    cudaGetSymbolAddress((void**)&lath, g_lath);

    cudaFuncSetAttribute(flash_f16, cudaFuncAttributeMaxDynamicSharedMemorySize,
                         FA6_BYTES);

    // conversions + packed-weight precompute
    convert_all<<<(CV_QUADS + 255) / 256, 256>>>(
        x, w_dq_w, w_dkv_w, w_uq_qr_w, w_uk_w, w_o_w, w_dq_b, w_dkv_b,
        xh, wqkv, wuq, wukn, wukv, woh, bqkv);
    beff_part_kernel<<<dim3(8, 16), 256>>>(w_o_w, w_uk_b, beffp);
    beff_reduce_kernel<<<4, 256>>>(beffp, w_o_b, beff);
    hgemm_pack<<<dim3(8, 1, 8), 256>>>(wukv, woh, wpack);

    // fused down projection
    hgemm<64, false><<<dim3(5, 32), 256>>>(xh, wqkv, bqkv, dqkv, T_TOK, 320, DIMM);
    // rmsnorm + k rope
    norm_rope_kernel<<<T_TOK, 128>>>(dqkv, q_norm_w, kv_norm_w, pos, cqh, ckvh, kr);
    // up projections (q full; kv -> k_nope only)
    hgemm<128, true><<<dim3(8, 32), 256>>>(cqh, wuq, w_uq_qr_b, qrawh, T_TOK, 1024, QC);
    hgemm<128, true><<<dim3(4, 32), 256>>>(ckvh, wukn, w_uk_b, knh, T_TOK, 512, KVC);
    // build per-head states + latent transpose
    scatter_qk<<<T_TOK, 256>>>(qrawh, knh, kr, pos, gq, gk);
    ckv_transpose<<<dim3(64, 4, 2), 256>>>(ckvh, ckvT);
    // attention in latent space
    flash_f16<<<dim3(S_LEN / 128, 16), 256, FA6_BYTES>>>(gq, gk, ckvT, lath);
    // absorbed output projection
    hgemm<128, false><<<dim3(8, 32), 256>>>(lath, wpack, beff, out, T_TOK, DIMM, 1024);
}